// round 4
// baseline (speedup 1.0000x reference)
#include <cuda_runtime.h>

#define BATCH 256
#define T 512
#define C 6
#define R 256
#define KS 128          // W_res rows staged in shared memory
#define KR 128          // W_res rows held in registers (64 packed f32x2 per thread)
#define BC 2            // batches per CTA
#define NBLK (BATCH/BC) // 128 CTAs, one wave on 148 SMs
#define NGS (KS/4)      // 32 smem k-groups of 4
#define NGR (KR/4)      // 32 register k-groups of 4

typedef unsigned long long ull;

// Packed 2xfp32 FMA (sm_100+): d.lane = a.lane * b.lane + d.lane
__device__ __forceinline__ void fma2(ull& d, ull a, ull b) {
    asm("fma.rn.f32x2 %0, %1, %2, %0;" : "+l"(d) : "l"(a), "l"(b));
}
__device__ __forceinline__ float sum2(ull a) {
    float lo, hi;
    asm("mov.b64 {%0,%1}, %2;" : "=f"(lo), "=f"(hi) : "l"(a));
    return lo + hi;
}
__device__ __forceinline__ ull pack2(float lo, float hi) {
    ull u; asm("mov.b64 %0, {%1,%2};" : "=l"(u) : "f"(lo), "f"(hi));
    return u;
}
// tanh(z) = 1 - 2/(exp(2z)+1): no inf/inf NaN (exp->inf gives exactly 1),
// abs error ~1e-7 which is far below the 1e-3 harness threshold.
__device__ __forceinline__ float tanh_fast(float z) {
    float e = __expf(2.0f * z);
    return 1.0f - __fdividef(2.0f, e + 1.0f);
}

__global__ void __launch_bounds__(R, 1)
esn_kernel(const float* __restrict__ x, const float* __restrict__ W_in,
           const float* __restrict__ W_res, float* __restrict__ out)
{
    extern __shared__ float sm[];
    float* Ws = sm;              // [NGS][R][4] : W rows [0,KS) grouped 4-k per float4
    float* hb = sm + KS * R;     // [2][BC][R]  : double-buffered hidden state

    const int r  = threadIdx.x;          // this thread owns output column r
    const int b0 = blockIdx.x * BC;      // first batch row of this CTA

    // Stage W rows [0, KS) into smem. Layout: Ws[(g*R + r)*4 + j] = W[4g+j][r]
    // so one LDS.128 per thread yields W[4g..4g+3][r]; 16B stride across the
    // warp -> conflict-free.
    for (int k = 0; k < KS; ++k)
        Ws[((k >> 2) * R + r) * 4 + (k & 3)] = W_res[k * R + r];

    // W rows [KS, 256) live in registers, packed in k-pairs for FFMA2.
    ull wreg[KR / 2];
    #pragma unroll
    for (int j = 0; j < KR / 2; ++j)
        wreg[j] = pack2(W_res[(KS + 2 * j) * R + r],
                        W_res[(KS + 2 * j + 1) * R + r]);

    float win[C];
    #pragma unroll
    for (int c = 0; c < C; ++c) win[c] = W_in[c * R + r];

    // h0 = 0 in buffer 0
    hb[r]     = 0.0f;
    hb[R + r] = 0.0f;
    __syncthreads();

    const float2* __restrict__ x0 = (const float2*)(x + (size_t)b0 * T * C);
    const float2* __restrict__ x1 = (const float2*)(x + (size_t)(b0 + 1) * T * C);
    float* __restrict__ o0 = out + (size_t)b0 * T * R + r;
    float* __restrict__ o1 = out + (size_t)(b0 + 1) * T * R + r;

    for (int t = 0; t < T; ++t) {
        // Kick off this step's input loads early; consumed ~2000 cycles later
        // in the epilogue, so gmem latency is fully hidden by the k-loop.
        float2 xa = x0[3 * t], xb = x0[3 * t + 1], xc = x0[3 * t + 2];
        float2 xd = x1[3 * t], xe = x1[3 * t + 1], xf = x1[3 * t + 2];

        const float* hcur = hb + (t & 1) * (BC * R);

        // 4 independent accumulator chains (2 batches x 2 k-group parities).
        // Lanes of each ull carry even/odd-k partial sums.
        ull aA0 = 0, aB0 = 0, aA1 = 0, aB1 = 0;

        #pragma unroll
        for (int g = 0; g < NGS; ++g) {
            ulonglong2 w  = *(const ulonglong2*)(Ws + (g * R + r) * 4);
            ulonglong2 h0 = *(const ulonglong2*)(hcur + 4 * g);          // broadcast
            ulonglong2 h1 = *(const ulonglong2*)(hcur + R + 4 * g);      // broadcast
            fma2(aA0, h0.x, w.x); fma2(aB0, h0.y, w.y);
            fma2(aA1, h1.x, w.x); fma2(aB1, h1.y, w.y);
        }
        #pragma unroll
        for (int g = 0; g < NGR; ++g) {
            ulonglong2 h0 = *(const ulonglong2*)(hcur + KS + 4 * g);     // broadcast
            ulonglong2 h1 = *(const ulonglong2*)(hcur + R + KS + 4 * g); // broadcast
            fma2(aA0, h0.x, wreg[2 * g]);     fma2(aB0, h0.y, wreg[2 * g + 1]);
            fma2(aA1, h1.x, wreg[2 * g]);     fma2(aB1, h1.y, wreg[2 * g + 1]);
        }

        // Input projection (C=6) for both batches.
        float xp0 = xa.x * win[0] + xa.y * win[1] + xb.x * win[2]
                  + xb.y * win[3] + xc.x * win[4] + xc.y * win[5];
        float xp1 = xd.x * win[0] + xd.y * win[1] + xe.x * win[2]
                  + xe.y * win[3] + xf.x * win[4] + xf.y * win[5];

        float z0 = sum2(aA0) + sum2(aB0) + xp0;
        float z1 = sum2(aA1) + sum2(aB1) + xp1;
        float h0n = tanh_fast(z0);
        float h1n = tanh_fast(z1);

        // Write next h into the other buffer (no WAR hazard with hcur reads),
        // then one barrier per step publishes it.
        float* hnxt = hb + ((t + 1) & 1) * (BC * R);
        hnxt[r]     = h0n;
        hnxt[R + r] = h1n;

        o0[(size_t)t * R] = h0n;   // coalesced: consecutive r across the warp
        o1[(size_t)t * R] = h1n;

        __syncthreads();
    }
}

extern "C" void kernel_launch(void* const* d_in, const int* in_sizes, int n_in,
                              void* d_out, int out_size) {
    const float* x     = (const float*)d_in[0];
    const float* W_in  = (const float*)d_in[1];
    const float* W_res = (const float*)d_in[2];
    float* out = (float*)d_out;

    const size_t smem_bytes = (size_t)(KS * R + 2 * BC * R) * sizeof(float); // 135168
    cudaFuncSetAttribute(esn_kernel, cudaFuncAttributeMaxDynamicSharedMemorySize,
                         (int)smem_bytes);
    esn_kernel<<<NBLK, R, smem_bytes>>>(x, W_in, W_res, out);
}

// round 5
// speedup vs baseline: 1.5490x; 1.5490x over previous
#include <cuda_runtime.h>

#define T 512
#define C 6
#define R 256
#define BC 2
#define NBLK 128        // 128 CTAs x 2 batches, one wave
#define WSM_ULL (64*256)

typedef unsigned long long ull;

// Packed 2xfp32 FMA (sm_100+): d.lane += a.lane * b.lane
__device__ __forceinline__ void fma2(ull& d, ull a, ull b) {
    asm("fma.rn.f32x2 %0, %1, %2, %0;" : "+l"(d) : "l"(a), "l"(b));
}
__device__ __forceinline__ float sum2(ull a) {
    float lo, hi;
    asm("mov.b64 {%0,%1}, %2;" : "=f"(lo), "=f"(hi) : "l"(a));
    return lo + hi;
}
__device__ __forceinline__ ull pack2(float lo, float hi) {
    ull u; asm("mov.b64 %0, {%1,%2};" : "=l"(u) : "f"(lo), "f"(hi));
    return u;
}
// tanh(z) = 1 - 2/(exp(2z)+1): exp->inf gives exactly 1 (no NaN); abs err ~1e-7.
__device__ __forceinline__ float tanh_fast(float z) {
    float e = __expf(2.0f * z);
    return 1.0f - __fdividef(2.0f, e + 1.0f);
}

// Split-K layout:
//   warp w owns k in [32w, 32w+32)  = k-pairs [16w, 16w+16)
//     pairs 0..7  of the warp -> registers (wreg, 64 ull)
//     pairs 8..15 of the warp -> smem Wsm[w*8 + j][r] (pair-packed ull)
//   thread lane l owns outputs r(g,s) = 64g + 2l + s,  g=0..3, s=0..1
// smem: Wsm ull[64][256] (128KB) | hsm float[2][256] (2KB) | red float[8][512] (16KB)
__global__ void __launch_bounds__(256, 1)
esn_kernel(const float* __restrict__ x, const float* __restrict__ W_in,
           const float* __restrict__ W_res, float* __restrict__ out)
{
    extern __shared__ char smraw[];
    ull*   Wsm = (ull*)smraw;
    float* hsm = (float*)(Wsm + WSM_ULL);
    float* red = hsm + 2 * R;

    const int tid = threadIdx.x;
    const int w = tid >> 5, l = tid & 31;
    const int b0 = blockIdx.x * BC;

    // Stage smem half of W, pair-packed: Wsm[sp][r] = (W[k0][r], W[k0+1][r]),
    // sp = wp*8 + j, k0 = 32*wp + 16 + 2*j.  Coalesced gmem reads (r = tid).
    for (int sp = 0; sp < 64; ++sp) {
        int wp = sp >> 3, j = sp & 7;
        int k0 = 32 * wp + 16 + 2 * j;
        Wsm[sp * R + tid] = pack2(W_res[k0 * R + tid], W_res[(k0 + 1) * R + tid]);
    }
    // Register half: pairs j=0..7 -> k0 = 32w + 2j, this thread's 8 r's.
    ull wreg[64];
    #pragma unroll
    for (int j = 0; j < 8; ++j) {
        int k0 = 32 * w + 2 * j;
        #pragma unroll
        for (int g = 0; g < 4; ++g) {
            int r0 = 64 * g + 2 * l;
            wreg[j * 8 + 2 * g + 0] = pack2(W_res[k0 * R + r0],     W_res[(k0 + 1) * R + r0]);
            wreg[j * 8 + 2 * g + 1] = pack2(W_res[k0 * R + r0 + 1], W_res[(k0 + 1) * R + r0 + 1]);
        }
    }
    float win[C];
    #pragma unroll
    for (int c = 0; c < C; ++c) win[c] = W_in[c * R + tid];

    hsm[tid] = 0.0f; hsm[R + tid] = 0.0f;
    __syncthreads();

    const float2* __restrict__ x0 = (const float2*)(x + (size_t)b0 * T * C);
    const float2* __restrict__ x1 = (const float2*)(x + (size_t)(b0 + 1) * T * C);
    float* __restrict__ o0 = out + (size_t)b0 * T * R + tid;
    float* __restrict__ o1 = out + (size_t)(b0 + 1) * T * R + tid;

    // Warp-uniform h slice pointers (broadcast LDS, 1 wavefront each).
    const ulonglong2* hp0 = (const ulonglong2*)(hsm + 32 * w);
    const ulonglong2* hp1 = (const ulonglong2*)(hsm + R + 32 * w);
    const ulonglong2* Wp  = (const ulonglong2*)(Wsm + (size_t)w * 8 * R);

    for (int t = 0; t < T; ++t) {
        // Input loads issued early; consumed ~1500 cycles later.
        float2 xa = x0[3 * t], xb = x0[3 * t + 1], xc = x0[3 * t + 2];
        float2 xd = x1[3 * t], xe = x1[3 * t + 1], xf = x1[3 * t + 2];

        // acc[(2g+s)*2 + b] : lanes carry (even-k, odd-k) partials for r(g,s), batch b.
        ull acc[16];
        #pragma unroll
        for (int i = 0; i < 16; ++i) acc[i] = 0;

        #pragma unroll
        for (int q = 0; q < 8; ++q) {          // q = one ulonglong2 h-chunk = k-pairs 2q, 2q+1
            ulonglong2 ha = hp0[q];            // batch0: (.x = pair 2q, .y = pair 2q+1)
            ulonglong2 hb = hp1[q];            // batch1
            if (q < 4) {
                // register half: pairs 2q, 2q+1
                #pragma unroll
                for (int gs = 0; gs < 8; ++gs) {
                    fma2(acc[gs * 2 + 0], ha.x, wreg[(2 * q) * 8 + gs]);
                    fma2(acc[gs * 2 + 1], hb.x, wreg[(2 * q) * 8 + gs]);
                    fma2(acc[gs * 2 + 0], ha.y, wreg[(2 * q + 1) * 8 + gs]);
                    fma2(acc[gs * 2 + 1], hb.y, wreg[(2 * q + 1) * 8 + gs]);
                }
            } else {
                // smem half: local pairs j0 = 2(q-4), j1 = j0+1
                const int j0 = 2 * (q - 4), j1 = j0 + 1;
                #pragma unroll
                for (int g = 0; g < 4; ++g) {
                    // conflict-free: lane l reads 16B at consecutive addresses
                    ulonglong2 wA = Wp[(j0 * R + 64 * g + 2 * l) >> 1]; // (r0, r0+1) of pair j0
                    ulonglong2 wB = Wp[(j1 * R + 64 * g + 2 * l) >> 1]; // (r0, r0+1) of pair j1
                    fma2(acc[(2 * g + 0) * 2 + 0], ha.x, wA.x);
                    fma2(acc[(2 * g + 1) * 2 + 0], ha.x, wA.y);
                    fma2(acc[(2 * g + 0) * 2 + 1], hb.x, wA.x);
                    fma2(acc[(2 * g + 1) * 2 + 1], hb.x, wA.y);
                    fma2(acc[(2 * g + 0) * 2 + 0], ha.y, wB.x);
                    fma2(acc[(2 * g + 1) * 2 + 0], ha.y, wB.y);
                    fma2(acc[(2 * g + 0) * 2 + 1], hb.y, wB.x);
                    fma2(acc[(2 * g + 1) * 2 + 1], hb.y, wB.y);
                }
            }
        }

        // Publish partials: red[w][2r + b], float4 per g (r0 b0, r0 b1, r0+1 b0, r0+1 b1).
        #pragma unroll
        for (int g = 0; g < 4; ++g) {
            int r0 = 64 * g + 2 * l;
            float4 v;
            v.x = sum2(acc[(2 * g + 0) * 2 + 0]);
            v.y = sum2(acc[(2 * g + 0) * 2 + 1]);
            v.z = sum2(acc[(2 * g + 1) * 2 + 0]);
            v.w = sum2(acc[(2 * g + 1) * 2 + 1]);
            *(float4*)&red[w * 2 * R + 2 * r0] = v;
        }
        __syncthreads();

        // Thread tid = r: reduce 8 warps' partials, add input projection, tanh.
        float sx = 0.0f, sy = 0.0f;
        #pragma unroll
        for (int ww = 0; ww < 8; ++ww) {
            float2 v = *(const float2*)&red[ww * 2 * R + 2 * tid];
            sx += v.x; sy += v.y;
        }
        float xp0 = xa.x * win[0] + xa.y * win[1] + xb.x * win[2]
                  + xb.y * win[3] + xc.x * win[4] + xc.y * win[5];
        float xp1 = xd.x * win[0] + xd.y * win[1] + xe.x * win[2]
                  + xe.y * win[3] + xf.x * win[4] + xf.y * win[5];

        float h0n = tanh_fast(sx + xp0);
        float h1n = tanh_fast(sy + xp1);

        hsm[tid]     = h0n;        // consumed only by this thread's own warp next step
        hsm[R + tid] = h1n;
        o0[(size_t)t * R] = h0n;   // coalesced STG
        o1[(size_t)t * R] = h1n;

        __syncthreads();           // guards red reuse (and hsm) for step t+1
    }
}

extern "C" void kernel_launch(void* const* d_in, const int* in_sizes, int n_in,
                              void* d_out, int out_size) {
    const float* x     = (const float*)d_in[0];
    const float* W_in  = (const float*)d_in[1];
    const float* W_res = (const float*)d_in[2];
    float* out = (float*)d_out;

    // 64*256*8 (Wsm) + 2*256*4 (hsm) + 8*512*4 (red) = 149504 bytes
    const size_t smem_bytes = (size_t)WSM_ULL * sizeof(ull)
                            + (size_t)2 * R * sizeof(float)
                            + (size_t)8 * 2 * R * sizeof(float);
    cudaFuncSetAttribute(esn_kernel, cudaFuncAttributeMaxDynamicSharedMemorySize,
                         (int)smem_bytes);
    esn_kernel<<<NBLK, R, smem_bytes>>>(x, W_in, W_res, out);
}

// round 6
// speedup vs baseline: 1.5554x; 1.0042x over previous
#include <cuda_runtime.h>

#define T 512
#define C 6
#define R 256
#define BC 2
#define NBLK 128        // 128 CTAs x 2 batches, one wave
#define WSM_ULL (64*256)
#define REDN (8 * 2 * R)   // one red buffer: 8 warps x (2 floats per r)

typedef unsigned long long ull;

// Packed 2xfp32 FMA (sm_100+): d.lane += a.lane * b.lane
__device__ __forceinline__ void fma2(ull& d, ull a, ull b) {
    asm("fma.rn.f32x2 %0, %1, %2, %0;" : "+l"(d) : "l"(a), "l"(b));
}
__device__ __forceinline__ float sum2(ull a) {
    float lo, hi;
    asm("mov.b64 {%0,%1}, %2;" : "=f"(lo), "=f"(hi) : "l"(a));
    return lo + hi;
}
__device__ __forceinline__ ull pack2(float lo, float hi) {
    ull u; asm("mov.b64 %0, {%1,%2};" : "=l"(u) : "f"(lo), "f"(hi));
    return u;
}
// tanh(z) = 1 - 2/(exp(2z)+1): exp->inf gives exactly 1 (no NaN); abs err ~1e-7.
__device__ __forceinline__ float tanh_fast(float z) {
    float e = __expf(2.0f * z);
    return 1.0f - __fdividef(2.0f, e + 1.0f);
}

// Split-K layout:
//   warp w owns k in [32w, 32w+32) = k-pairs [16w, 16w+16)
//     pairs 0..7  of the warp -> registers (wreg, 64 ull)
//     pairs 8..15 of the warp -> smem Wsm[w*8 + j][r] (pair-packed ull)
//   lane l owns outputs r(g,s) = 64g + 2l + s,  g=0..3, s=0..1
//   h[r] is produced by thread r and consumed ONLY by warp r>>5 (same warp)
//     -> h round-trips through smem with __syncwarp only, no block barrier.
//   Partials cross warps through a PING-PONG red buffer -> ONE __syncthreads
//     per step; warps free-run across the phase2 tail of slower warps.
// smem: Wsm ull[64][256] (128KB) | hsm float[2][256] (2KB) | red float[2][8][512] (32KB)
__global__ void __launch_bounds__(256, 1)
esn_kernel(const float* __restrict__ x, const float* __restrict__ W_in,
           const float* __restrict__ W_res, float* __restrict__ out)
{
    extern __shared__ char smraw[];
    ull*   Wsm = (ull*)smraw;
    float* hsm  = (float*)(Wsm + WSM_ULL);
    float* red0 = hsm + 2 * R;
    float* red1 = red0 + REDN;

    const int tid = threadIdx.x;
    const int w = tid >> 5, l = tid & 31;
    const int b0 = blockIdx.x * BC;

    // Stage smem half of W, pair-packed: Wsm[sp][r] = (W[k0][r], W[k0+1][r]),
    // sp = wp*8 + j, k0 = 32*wp + 16 + 2*j.  Coalesced gmem reads (r = tid).
    for (int sp = 0; sp < 64; ++sp) {
        int wp = sp >> 3, j = sp & 7;
        int k0 = 32 * wp + 16 + 2 * j;
        Wsm[sp * R + tid] = pack2(W_res[k0 * R + tid], W_res[(k0 + 1) * R + tid]);
    }
    // Register half: pairs j=0..7 -> k0 = 32w + 2j, this thread's 8 r's.
    ull wreg[64];
    #pragma unroll
    for (int j = 0; j < 8; ++j) {
        int k0 = 32 * w + 2 * j;
        #pragma unroll
        for (int g = 0; g < 4; ++g) {
            int r0 = 64 * g + 2 * l;
            wreg[j * 8 + 2 * g + 0] = pack2(W_res[k0 * R + r0],     W_res[(k0 + 1) * R + r0]);
            wreg[j * 8 + 2 * g + 1] = pack2(W_res[k0 * R + r0 + 1], W_res[(k0 + 1) * R + r0 + 1]);
        }
    }
    float win[C];
    #pragma unroll
    for (int c = 0; c < C; ++c) win[c] = W_in[c * R + tid];

    hsm[tid] = 0.0f; hsm[R + tid] = 0.0f;
    __syncthreads();

    const float2* __restrict__ x0 = (const float2*)(x + (size_t)b0 * T * C);
    const float2* __restrict__ x1 = (const float2*)(x + (size_t)(b0 + 1) * T * C);
    float* __restrict__ o0 = out + (size_t)b0 * T * R + tid;
    float* __restrict__ o1 = out + (size_t)(b0 + 1) * T * R + tid;

    // Warp-uniform h slice pointers (broadcast LDS, 1 wavefront each).
    const ulonglong2* hp0 = (const ulonglong2*)(hsm + 32 * w);
    const ulonglong2* hp1 = (const ulonglong2*)(hsm + R + 32 * w);
    const ulonglong2* Wp  = (const ulonglong2*)(Wsm + (size_t)w * 8 * R);

    for (int t = 0; t < T; ++t) {
        float* redc = (t & 1) ? red1 : red0;   // ping-pong partials buffer

        // Input loads issued early; consumed ~1500 cycles later.
        float2 xa = x0[3 * t], xb = x0[3 * t + 1], xc = x0[3 * t + 2];
        float2 xd = x1[3 * t], xe = x1[3 * t + 1], xf = x1[3 * t + 2];

        // acc[(2g+s)*2 + b] : lanes carry (even-k, odd-k) partials for r(g,s), batch b.
        ull acc[16];
        #pragma unroll
        for (int i = 0; i < 16; ++i) acc[i] = 0;

        #pragma unroll
        for (int q = 0; q < 8; ++q) {          // q = one ulonglong2 h-chunk = k-pairs 2q, 2q+1
            ulonglong2 ha = hp0[q];            // batch0: (.x = pair 2q, .y = pair 2q+1)
            ulonglong2 hb = hp1[q];            // batch1
            if (q < 4) {
                // register half: pairs 2q, 2q+1
                #pragma unroll
                for (int gs = 0; gs < 8; ++gs) {
                    fma2(acc[gs * 2 + 0], ha.x, wreg[(2 * q) * 8 + gs]);
                    fma2(acc[gs * 2 + 1], hb.x, wreg[(2 * q) * 8 + gs]);
                    fma2(acc[gs * 2 + 0], ha.y, wreg[(2 * q + 1) * 8 + gs]);
                    fma2(acc[gs * 2 + 1], hb.y, wreg[(2 * q + 1) * 8 + gs]);
                }
            } else {
                // smem half: local pairs j0 = 2(q-4), j1 = j0+1
                const int j0 = 2 * (q - 4), j1 = j0 + 1;
                #pragma unroll
                for (int g = 0; g < 4; ++g) {
                    // conflict-free: lane l reads 16B at consecutive addresses
                    ulonglong2 wA = Wp[(j0 * R + 64 * g + 2 * l) >> 1]; // (r0, r0+1) of pair j0
                    ulonglong2 wB = Wp[(j1 * R + 64 * g + 2 * l) >> 1]; // (r0, r0+1) of pair j1
                    fma2(acc[(2 * g + 0) * 2 + 0], ha.x, wA.x);
                    fma2(acc[(2 * g + 1) * 2 + 0], ha.x, wA.y);
                    fma2(acc[(2 * g + 0) * 2 + 1], hb.x, wA.x);
                    fma2(acc[(2 * g + 1) * 2 + 1], hb.x, wA.y);
                    fma2(acc[(2 * g + 0) * 2 + 0], ha.y, wB.x);
                    fma2(acc[(2 * g + 1) * 2 + 0], ha.y, wB.y);
                    fma2(acc[(2 * g + 0) * 2 + 1], hb.y, wB.x);
                    fma2(acc[(2 * g + 1) * 2 + 1], hb.y, wB.y);
                }
            }
        }

        // Input projection (off the phase2 critical path).
        float xp0 = xa.x * win[0] + xa.y * win[1] + xb.x * win[2]
                  + xb.y * win[3] + xc.x * win[4] + xc.y * win[5];
        float xp1 = xd.x * win[0] + xd.y * win[1] + xe.x * win[2]
                  + xe.y * win[3] + xf.x * win[4] + xf.y * win[5];

        // Publish partials: red[w][2r + b], float4 per g (r0 b0, r0 b1, r0+1 b0, r0+1 b1).
        #pragma unroll
        for (int g = 0; g < 4; ++g) {
            int r0 = 64 * g + 2 * l;
            float4 v;
            v.x = sum2(acc[(2 * g + 0) * 2 + 0]);
            v.y = sum2(acc[(2 * g + 0) * 2 + 1]);
            v.z = sum2(acc[(2 * g + 1) * 2 + 0]);
            v.w = sum2(acc[(2 * g + 1) * 2 + 1]);
            *(float4*)&redc[w * 2 * R + 2 * r0] = v;
        }

        // Single block barrier per step: orders partials STS -> reduce LDS.
        // Also orders this step's hsm reads (above) before the hsm writes (below).
        __syncthreads();

        // Thread tid = r: reduce 8 warps' partials, add input projection, tanh.
        float sx = 0.0f, sy = 0.0f;
        #pragma unroll
        for (int ww = 0; ww < 8; ++ww) {
            float2 v = *(const float2*)&redc[ww * 2 * R + 2 * tid];
            sx += v.x; sy += v.y;
        }
        float h0n = tanh_fast(sx + xp0);
        float h1n = tanh_fast(sy + xp1);

        hsm[tid]     = h0n;        // consumed next step ONLY by this thread's own warp
        hsm[R + tid] = h1n;
        o0[(size_t)t * R] = h0n;   // coalesced STG
        o1[(size_t)t * R] = h1n;

        __syncwarp();              // intra-warp visibility of hsm for next step
    }
}

extern "C" void kernel_launch(void* const* d_in, const int* in_sizes, int n_in,
                              void* d_out, int out_size) {
    const float* x     = (const float*)d_in[0];
    const float* W_in  = (const float*)d_in[1];
    const float* W_res = (const float*)d_in[2];
    float* out = (float*)d_out;

    // 128KB (Wsm) + 2KB (hsm) + 32KB (red x2) = 165888 bytes
    const size_t smem_bytes = (size_t)WSM_ULL * sizeof(ull)
                            + (size_t)2 * R * sizeof(float)
                            + (size_t)2 * REDN * sizeof(float);
    cudaFuncSetAttribute(esn_kernel, cudaFuncAttributeMaxDynamicSharedMemorySize,
                         (int)smem_bytes);
    esn_kernel<<<NBLK, R, smem_bytes>>>(x, W_in, W_res, out);
}